// round 2
// baseline (speedup 1.0000x reference)
#include <cuda_runtime.h>
#include <math.h>

#define BB   8
#define SEQ  2048
#define D    512
#define CWIN 16
#define NCH  128
#define DP   1536

// ---------------- persistent device scratch ----------------
__device__ float g_K[BB*SEQ*D];
__device__ float g_V[BB*SEQ*D];
__device__ float g_Q[BB*SEQ*D];
__device__ float g_Y[BB*SEQ*D];
__device__ float g_M[(size_t)BB*DP*D];
__device__ float g_S[(size_t)BB*DP*D];
__device__ float g_E[D*D];
__device__ float g_Xlast[BB*NCH*D];
__device__ float g_QG[BB*NCH*D];
__device__ float g_T[BB*NCH*D];
__device__ float g_gamma[BB*NCH*CWIN];
__device__ float g_alpha[BB*NCH];
__device__ float g_theta[BB*NCH];
__device__ float g_eta[BB*NCH];
__device__ float g_err[BB*CWIN*D];
__device__ float g_partial[BB*96];
__device__ float g_scaleA[BB];

__device__ __forceinline__ float wred(float x){
    #pragma unroll
    for (int o=16;o;o>>=1) x += __shfl_down_sync(0xffffffffu, x, o);
    return x;
}

// ---------------- generic fp32 GEMM ----------------
// NT=true : C[m,n] = sum_k A[m,k]*B[n,k]   (A:[M,K] rm, B:[N,K] rm)
// NT=false: C[m,n] = sum_k A[m,k]*B[k,n]   (A:[M,K] rm, B:[K,N] rm)
// M,N multiples of 128; K multiple of 16.
template<bool NT>
__global__ void __launch_bounds__(256) gemm_kernel(const float* __restrict__ A,
                                                   const float* __restrict__ Bm,
                                                   float* __restrict__ Cm,
                                                   int M, int N, int K)
{
    __shared__ float As[16][132];
    __shared__ float Bs[16][132];
    int tid = threadIdx.x;
    int m0 = blockIdx.y * 128, n0 = blockIdx.x * 128;
    int ty = tid >> 4, tx = tid & 15;
    float acc[8][8];
    #pragma unroll
    for (int i=0;i<8;i++)
        #pragma unroll
        for (int j=0;j<8;j++) acc[i][j]=0.f;

    for (int k0=0;k0<K;k0+=16){
        #pragma unroll
        for (int l=0;l<2;l++){
            int idx = tid + l*256;
            int row = idx >> 2, k4 = (idx & 3)*4;
            float4 av = *(const float4*)(A + (size_t)(m0+row)*K + k0 + k4);
            As[k4+0][row]=av.x; As[k4+1][row]=av.y; As[k4+2][row]=av.z; As[k4+3][row]=av.w;
        }
        if (NT){
            #pragma unroll
            for (int l=0;l<2;l++){
                int idx = tid + l*256;
                int row = idx >> 2, k4 = (idx & 3)*4;
                float4 bv = *(const float4*)(Bm + (size_t)(n0+row)*K + k0 + k4);
                Bs[k4+0][row]=bv.x; Bs[k4+1][row]=bv.y; Bs[k4+2][row]=bv.z; Bs[k4+3][row]=bv.w;
            }
        } else {
            #pragma unroll
            for (int l=0;l<2;l++){
                int idx = tid + l*256;
                int kr = idx >> 5, n4 = (idx & 31)*4;
                float4 bv = *(const float4*)(Bm + (size_t)(k0+kr)*N + n0 + n4);
                *(float4*)&Bs[kr][n4] = bv;
            }
        }
        __syncthreads();
        #pragma unroll
        for (int kk=0;kk<16;kk++){
            float a[8], b[8];
            *(float4*)(a)   = *(const float4*)&As[kk][ty*8];
            *(float4*)(a+4) = *(const float4*)&As[kk][ty*8+4];
            *(float4*)(b)   = *(const float4*)&Bs[kk][tx*8];
            *(float4*)(b+4) = *(const float4*)&Bs[kk][tx*8+4];
            #pragma unroll
            for (int i=0;i<8;i++)
                #pragma unroll
                for (int j=0;j<8;j++) acc[i][j] = fmaf(a[i], b[j], acc[i][j]);
        }
        __syncthreads();
    }
    #pragma unroll
    for (int i=0;i<8;i++){
        size_t r = (size_t)(m0 + ty*8 + i)*N + n0 + tx*8;
        *(float4*)(Cm + r)     = make_float4(acc[i][0],acc[i][1],acc[i][2],acc[i][3]);
        *(float4*)(Cm + r + 4) = make_float4(acc[i][4],acc[i][5],acc[i][6],acc[i][7]);
    }
}

// ---------------- gather last token of each chunk ----------------
__global__ void gather_xlast(const float* __restrict__ x){
    int i = blockIdx.x*256 + threadIdx.x;
    if (i < BB*NCH*D){
        int e = i & 511; int r = i >> 9; int b = r >> 7; int n = r & 127;
        g_Xlast[i] = x[((size_t)b*SEQ + n*CWIN + (CWIN-1))*D + e];
    }
}

__global__ void zero_partial(){
    int i = blockIdx.x*256 + threadIdx.x;
    if (i < BB*96) g_partial[i] = 0.f;
}

// ---------------- gates: gamma / alpha / theta / eta ----------------
__global__ void __launch_bounds__(128) gates_kernel(const float* __restrict__ x,
    const float* __restrict__ temp,
    const float* __restrict__ aw, const float* __restrict__ ab,
    const float* __restrict__ tw, const float* __restrict__ tb,
    const float* __restrict__ ew, const float* __restrict__ eb)
{
    int r = blockIdx.x; int b = r >> 7; int n = r & 127;
    int tid = threadIdx.x, w = tid >> 5, lane = tid & 31;
    __shared__ float ts[512];
    __shared__ float accA[16], accT[16], accE[16];
    for (int i=tid;i<512;i+=128) ts[i] = g_T[(size_t)r*512 + i];
    __syncthreads();
    float invt = 1.0f/(22.627416997969522f * fmaxf(temp[0], 0.1f));
    for (int c=w;c<16;c+=4){
        const float* xr = x + ((size_t)b*SEQ + n*CWIN + c)*D;
        float gs=0.f, as=0.f, tws=0.f, es=0.f;
        for (int e=lane;e<512;e+=32){
            float xv = xr[e];
            gs  = fmaf(xv, ts[e], gs);
            as  = fmaf(xv, aw[e], as);
            tws = fmaf(xv, tw[e], tws);
            es  = fmaf(xv, ew[e], es);
        }
        gs = wred(gs); as = wred(as); tws = wred(tws); es = wred(es);
        if (lane==0){
            g_gamma[(size_t)r*CWIN + c] = 1.f/(1.f + expf(-gs*invt));
            accA[c]=as; accT[c]=tws; accE[c]=es;
        }
    }
    __syncthreads();
    if (tid==0){
        float sa=0.f, st=0.f, se=0.f;
        for (int c=0;c<16;c++){ sa+=accA[c]; st+=accT[c]; se+=accE[c]; }
        sa = sa*(1.f/16.f) + ab[0];
        st = st*(1.f/16.f) + tb[0];
        se = se*(1.f/16.f) + eb[0];
        g_alpha[r] = 1.f/(1.f+expf(-sa));
        g_theta[r] = 1.f/(1.f+expf(-st));
        g_eta[r]   = 1.f/(1.f+expf(-se));
    }
}

// ---------------- chunk kernels ----------------
// kernAC<false>: pred + err for chunk n (uses previous M, scale s_prev from partials)
// kernAC<true> : y-read for chunk n     (uses new M,   scale s_n    from partials)
template<bool ISC>
__global__ void __launch_bounds__(256) kernAC(const float* __restrict__ KQ,
                                              const float* __restrict__ coeffs, int n)
{
    __shared__ float sh[8192];   // phase 1: k transposed [j][c]; phase 2: reduction scratch
    __shared__ float sps;
    int vt = blockIdx.x, b = blockIdx.y;
    int tid = threadIdx.x, w = tid >> 5, lane = tid & 31;
    int v = vt*32 + lane;

    const float* src = KQ + ((size_t)b*SEQ + n*CWIN)*D;
    #pragma unroll
    for (int i=tid;i<8192;i+=256){
        int c = i >> 9, j = i & 511;
        sh[j*16 + c] = src[i];
    }
    if (tid==0){
        float ss = 0.f;
        #pragma unroll 1
        for (int i=0;i<96;i++) ss += g_partial[b*96 + i];
        float s = fminf(50.0f/(sqrtf(ss) + 1e-6f), 1.0f);
        sps = s;
        if (!ISC && vt==0) g_scaleA[b] = s;
    }
    __syncthreads();

    float c0 = coeffs[0], c1 = coeffs[1], c2 = coeffs[2];
    const float* Mb = g_M + (size_t)b*DP*D;
    float acc[16];
    #pragma unroll
    for (int c=0;c<16;c++) acc[c]=0.f;
    float r0 = 0.f;
    int p0 = w*64;
    #pragma unroll 4
    for (int p=p0;p<p0+64;p++) r0 += Mb[(size_t)p*D + v];

    const float4* ks4 = (const float4*)sh;
    #pragma unroll 2
    for (int j=p0;j<p0+64;j++){
        float m1 = Mb[(size_t)(512 + j)*D + v];
        float m2 = Mb[(size_t)(1024 + j)*D + v];
        float t1 = c1*m1, t2 = c2*m2;
        float4 ka = ks4[j*4+0], kb = ks4[j*4+1], kc4 = ks4[j*4+2], kd = ks4[j*4+3];
        float kc[16] = {ka.x,ka.y,ka.z,ka.w, kb.x,kb.y,kb.z,kb.w,
                        kc4.x,kc4.y,kc4.z,kc4.w, kd.x,kd.y,kd.z,kd.w};
        #pragma unroll
        for (int c=0;c<16;c++) acc[c] = fmaf(kc[c], fmaf(kc[c], t2, t1), acc[c]);
    }
    float sloc = sps;
    __syncthreads();   // done reading k in sh

    #pragma unroll
    for (int c=0;c<16;c++) sh[(w*16 + c)*32 + lane] = acc[c];
    sh[4096 + w*32 + lane] = r0;
    __syncthreads();

    float R0 = 0.f;
    #pragma unroll
    for (int ww=0;ww<8;ww++) R0 += sh[4096 + ww*32 + lane];

    #pragma unroll
    for (int t=0;t<2;t++){
        int c = w + t*8;
        float p = 0.f;
        #pragma unroll
        for (int ww=0;ww<8;ww++) p += sh[(ww*16 + c)*32 + lane];
        p = (p + c0*R0) * sloc;
        if (ISC){
            g_Y[((size_t)b*SEQ + n*CWIN + c)*D + v] = p;
        } else {
            float vv = g_V[((size_t)b*SEQ + n*CWIN + c)*D + v];
            float e = g_gamma[(b*NCH + n)*CWIN + c] * (p - vv);
            g_err[((size_t)b*CWIN + c)*D + v] = e;
        }
    }
}

// grad + S/M update + per-block sumsq partial (deterministic, no atomics)
__global__ void __launch_bounds__(256) kernB(const float* __restrict__ Kbuf,
                                             const float* __restrict__ coeffs, int n)
{
    int pt = blockIdx.x, b = blockIdx.y;
    int tid = threadIdx.x;
    __shared__ float kl[16][16];
    __shared__ float wr[8];
    int type = pt < 32 ? 0 : (pt < 64 ? 1 : 2);
    if (type){
        int r = tid >> 4, c = tid & 15;
        int j = (type==1 ? (pt-32) : (pt-64))*16 + r;
        float kv = Kbuf[((size_t)b*SEQ + n*CWIN + c)*D + j];
        kl[r][c] = (type==1) ? kv : kv*kv;
    }
    __syncthreads();

    int idx = b*NCH + n;
    float al = g_alpha[idx] * g_scaleA[b];
    float th = g_theta[idx];
    float et = g_eta[idx];
    float f  = 0.125f * (type==0 ? coeffs[0] : (type==1 ? coeffs[1] : coeffs[2]));

    float e0[16], e1[16];
    #pragma unroll
    for (int c=0;c<16;c++){
        e0[c] = g_err[((size_t)b*CWIN + c)*D + tid];
        e1[c] = g_err[((size_t)b*CWIN + c)*D + tid + 256];
    }
    float g0c = 0.f, g1c = 0.f;
    if (type==0){
        #pragma unroll
        for (int c=0;c<16;c++){ g0c += e0[c]; g1c += e1[c]; }
        g0c *= f; g1c *= f;
    }

    float sq = 0.f;
    for (int r=0;r<16;r++){
        size_t rb = ((size_t)b*DP + (size_t)pt*16 + r)*D;
        float g0, g1;
        if (type==0){ g0 = g0c; g1 = g1c; }
        else {
            g0 = 0.f; g1 = 0.f;
            #pragma unroll
            for (int c=0;c<16;c++){
                float kv = kl[r][c];
                g0 = fmaf(kv, e0[c], g0);
                g1 = fmaf(kv, e1[c], g1);
            }
            g0 *= f; g1 *= f;
        }
        float so0 = g_S[rb + tid],        so1 = g_S[rb + tid + 256];
        float mo0 = g_M[rb + tid],        mo1 = g_M[rb + tid + 256];
        float sn0 = th*so0 - et*g0,       sn1 = th*so1 - et*g1;
        float mn0 = fmaf(al, mo0, sn0),   mn1 = fmaf(al, mo1, sn1);
        g_S[rb + tid] = sn0;  g_S[rb + tid + 256] = sn1;
        g_M[rb + tid] = mn0;  g_M[rb + tid + 256] = mn1;
        sq += mn0*mn0 + mn1*mn1;
    }
    sq = wred(sq);
    if ((tid & 31) == 0) wr[tid >> 5] = sq;
    __syncthreads();
    if (tid==0){
        float s = 0.f;
        for (int i=0;i<8;i++) s += wr[i];
        g_partial[b*96 + pt] = s;
    }
}

// ---------------- launch ----------------
extern "C" void kernel_launch(void* const* d_in, const int* in_sizes, int n_in,
                              void* d_out, int out_size)
{
    const float* x     = (const float*)d_in[0];
    const float* M0    = (const float*)d_in[1];
    const float* S0    = (const float*)d_in[2];
    const float* Wk    = (const float*)d_in[3];
    const float* Wv    = (const float*)d_in[4];
    const float* Wq    = (const float*)d_in[5];
    const float* Wqk   = (const float*)d_in[6];
    const float* Wout  = (const float*)d_in[7];
    const float* coeffs= (const float*)d_in[8];
    const float* cgWq  = (const float*)d_in[9];
    const float* cgWk  = (const float*)d_in[10];
    const float* temp  = (const float*)d_in[11];
    const float* aw    = (const float*)d_in[12];
    const float* ab    = (const float*)d_in[13];
    const float* tw    = (const float*)d_in[14];
    const float* tb    = (const float*)d_in[15];
    const float* ew    = (const float*)d_in[16];
    const float* eb    = (const float*)d_in[17];
    float* out = (float*)d_out;

    float *pM,*pS,*pK,*pV,*pQ,*pY,*pE,*pXl,*pQG,*pT;
    cudaGetSymbolAddress((void**)&pM,  g_M);
    cudaGetSymbolAddress((void**)&pS,  g_S);
    cudaGetSymbolAddress((void**)&pK,  g_K);
    cudaGetSymbolAddress((void**)&pV,  g_V);
    cudaGetSymbolAddress((void**)&pQ,  g_Q);
    cudaGetSymbolAddress((void**)&pY,  g_Y);
    cudaGetSymbolAddress((void**)&pE,  g_E);
    cudaGetSymbolAddress((void**)&pXl, g_Xlast);
    cudaGetSymbolAddress((void**)&pQG, g_QG);
    cudaGetSymbolAddress((void**)&pT,  g_T);

    cudaMemcpyAsync(pM, M0, sizeof(float)*(size_t)BB*DP*D, cudaMemcpyDeviceToDevice);
    cudaMemcpyAsync(pS, S0, sizeof(float)*(size_t)BB*DP*D, cudaMemcpyDeviceToDevice);
    zero_partial<<<3,256>>>();

    // fold Wqk@Wq, then the big projections
    gemm_kernel<false><<<dim3(4,4),  256>>>(Wqk, Wq,  pE, 512,   512, 512);
    gemm_kernel<true ><<<dim3(4,128),256>>>(x,   Wk,  pK, BB*SEQ,512, 512);
    gemm_kernel<true ><<<dim3(4,128),256>>>(x,   Wv,  pV, BB*SEQ,512, 512);
    gemm_kernel<true ><<<dim3(4,128),256>>>(x,   pE,  pQ, BB*SEQ,512, 512);

    // gates: qg = xlast@cgWq^T ; t = qg@cgWk ; gamma/alpha/theta/eta
    gather_xlast<<<2048,256>>>(x);
    gemm_kernel<true ><<<dim3(4,8),256>>>(pXl, cgWq, pQG, BB*NCH, 512, 512);
    gemm_kernel<false><<<dim3(4,8),256>>>(pQG, cgWk, pT,  BB*NCH, 512, 512);
    gates_kernel<<<BB*NCH,128>>>(x, temp, aw, ab, tw, tb, ew, eb);

    // sequential chunk recurrence
    for (int n=0;n<NCH;n++){
        kernAC<false><<<dim3(16,8),256>>>(pK, coeffs, n);
        kernB        <<<dim3(96,8),256>>>(pK, coeffs, n);
        kernAC<true ><<<dim3(16,8),256>>>(pQ, coeffs, n);
    }

    // out = Y @ Wout^T
    gemm_kernel<true><<<dim3(4,128),256>>>(pY, Wout, out, BB*SEQ, 512, 512);
}

// round 3
// speedup vs baseline: 1.8248x; 1.8248x over previous
#include <cuda_runtime.h>
#include <math.h>

#define BB   8
#define SEQ  2048
#define D    512
#define CWIN 16
#define NCH  128
#define DP   1536

// ---------------- persistent device scratch ----------------
__device__ float g_K[BB*SEQ*D];
__device__ float g_V[BB*SEQ*D];
__device__ float g_Q[BB*SEQ*D];
__device__ float g_Y[BB*SEQ*D];
__device__ float g_M[(size_t)BB*DP*D];
__device__ float g_S[(size_t)BB*DP*D];
__device__ float g_E[D*D];
__device__ float g_Xlast[BB*NCH*D];
__device__ float g_QG[BB*NCH*D];
__device__ float g_T[BB*NCH*D];
__device__ float g_gamma[BB*NCH*CWIN];
__device__ float g_alpha[BB*NCH];
__device__ float g_theta[BB*NCH];
__device__ float g_eta[BB*NCH];
__device__ float g_part2[BB*16];
__device__ unsigned int g_ctr[BB];

__device__ __forceinline__ float wred(float x){
    #pragma unroll
    for (int o=16;o;o>>=1) x += __shfl_down_sync(0xffffffffu, x, o);
    return x;
}

// ---------------- generic fp32 GEMM ----------------
template<bool NT>
__global__ void __launch_bounds__(256) gemm_kernel(const float* __restrict__ A,
                                                   const float* __restrict__ Bm,
                                                   float* __restrict__ Cm,
                                                   int M, int N, int K)
{
    __shared__ float As[16][132];
    __shared__ float Bs[16][132];
    int tid = threadIdx.x;
    int m0 = blockIdx.y * 128, n0 = blockIdx.x * 128;
    int ty = tid >> 4, tx = tid & 15;
    float acc[8][8];
    #pragma unroll
    for (int i=0;i<8;i++)
        #pragma unroll
        for (int j=0;j<8;j++) acc[i][j]=0.f;

    for (int k0=0;k0<K;k0+=16){
        #pragma unroll
        for (int l=0;l<2;l++){
            int idx = tid + l*256;
            int row = idx >> 2, k4 = (idx & 3)*4;
            float4 av = *(const float4*)(A + (size_t)(m0+row)*K + k0 + k4);
            As[k4+0][row]=av.x; As[k4+1][row]=av.y; As[k4+2][row]=av.z; As[k4+3][row]=av.w;
        }
        if (NT){
            #pragma unroll
            for (int l=0;l<2;l++){
                int idx = tid + l*256;
                int row = idx >> 2, k4 = (idx & 3)*4;
                float4 bv = *(const float4*)(Bm + (size_t)(n0+row)*K + k0 + k4);
                Bs[k4+0][row]=bv.x; Bs[k4+1][row]=bv.y; Bs[k4+2][row]=bv.z; Bs[k4+3][row]=bv.w;
            }
        } else {
            #pragma unroll
            for (int l=0;l<2;l++){
                int idx = tid + l*256;
                int kr = idx >> 5, n4 = (idx & 31)*4;
                float4 bv = *(const float4*)(Bm + (size_t)(k0+kr)*N + n0 + n4);
                *(float4*)&Bs[kr][n4] = bv;
            }
        }
        __syncthreads();
        #pragma unroll
        for (int kk=0;kk<16;kk++){
            float a[8], b[8];
            *(float4*)(a)   = *(const float4*)&As[kk][ty*8];
            *(float4*)(a+4) = *(const float4*)&As[kk][ty*8+4];
            *(float4*)(b)   = *(const float4*)&Bs[kk][tx*8];
            *(float4*)(b+4) = *(const float4*)&Bs[kk][tx*8+4];
            #pragma unroll
            for (int i=0;i<8;i++)
                #pragma unroll
                for (int j=0;j<8;j++) acc[i][j] = fmaf(a[i], b[j], acc[i][j]);
        }
        __syncthreads();
    }
    #pragma unroll
    for (int i=0;i<8;i++){
        size_t r = (size_t)(m0 + ty*8 + i)*N + n0 + tx*8;
        *(float4*)(Cm + r)     = make_float4(acc[i][0],acc[i][1],acc[i][2],acc[i][3]);
        *(float4*)(Cm + r + 4) = make_float4(acc[i][4],acc[i][5],acc[i][6],acc[i][7]);
    }
}

// ---------------- gather last token of each chunk ----------------
__global__ void gather_xlast(const float* __restrict__ x){
    int i = blockIdx.x*256 + threadIdx.x;
    if (i < BB*NCH*D){
        int e = i & 511; int r = i >> 9; int b = r >> 7; int n = r & 127;
        g_Xlast[i] = x[((size_t)b*SEQ + n*CWIN + (CWIN-1))*D + e];
    }
}

__global__ void zero_ctrs(){
    int i = threadIdx.x;
    if (i < BB*16) g_part2[i] = 0.f;
    if (i < BB)    g_ctr[i]   = 0u;
}

// ---------------- gates: gamma / alpha / theta / eta ----------------
__global__ void __launch_bounds__(128) gates_kernel(const float* __restrict__ x,
    const float* __restrict__ temp,
    const float* __restrict__ aw, const float* __restrict__ ab,
    const float* __restrict__ tw, const float* __restrict__ tb,
    const float* __restrict__ ew, const float* __restrict__ eb)
{
    int r = blockIdx.x; int b = r >> 7; int n = r & 127;
    int tid = threadIdx.x, w = tid >> 5, lane = tid & 31;
    __shared__ float ts[512];
    __shared__ float accA[16], accT[16], accE[16];
    for (int i=tid;i<512;i+=128) ts[i] = g_T[(size_t)r*512 + i];
    __syncthreads();
    float invt = 1.0f/(22.627416997969522f * fmaxf(temp[0], 0.1f));
    for (int c=w;c<16;c+=4){
        const float* xr = x + ((size_t)b*SEQ + n*CWIN + c)*D;
        float gs=0.f, as=0.f, tws=0.f, es=0.f;
        for (int e=lane;e<512;e+=32){
            float xv = xr[e];
            gs  = fmaf(xv, ts[e], gs);
            as  = fmaf(xv, aw[e], as);
            tws = fmaf(xv, tw[e], tws);
            es  = fmaf(xv, ew[e], es);
        }
        gs = wred(gs); as = wred(as); tws = wred(tws); es = wred(es);
        if (lane==0){
            g_gamma[(size_t)r*CWIN + c] = 1.f/(1.f + expf(-gs*invt));
            accA[c]=as; accT[c]=tws; accE[c]=es;
        }
    }
    __syncthreads();
    if (tid==0){
        float sa=0.f, st=0.f, se=0.f;
        for (int c=0;c<16;c++){ sa+=accA[c]; st+=accT[c]; se+=accE[c]; }
        sa = sa*(1.f/16.f) + ab[0];
        st = st*(1.f/16.f) + tb[0];
        se = se*(1.f/16.f) + eb[0];
        g_alpha[r] = 1.f/(1.f+expf(-sa));
        g_theta[r] = 1.f/(1.f+expf(-st));
        g_eta[r]   = 1.f/(1.f+expf(-se));
    }
}

// ---------------- persistent chunk-recurrence kernel ----------------
// grid (16,8): block (vt,b) owns v-stripe [vt*32, vt*32+32) of M,S for batch b
// across ALL 128 chunks. Only cross-block coupling: scalar norm per chunk,
// exchanged via a per-batch atomic-counter barrier (16 blocks, all co-resident:
// 128 blocks <= 148 SMs, 1 block/SM).
__global__ void __launch_bounds__(512) chunk_loop_kernel(const float* __restrict__ coeffs)
{
    extern __shared__ float sm[];
    float2* ks2 = (float2*)sm;                 // [16][512] (k, k^2)      65536 B
    float2* qs2 = (float2*)(sm + 16384);       // [16][512] (c1 q, c2 q^2) 65536 B
    float*  red = sm + 32768;                  // [16][16][32]             32768 B
    float*  r0r = sm + 40960;                  // [16][32]                  2048 B
    float*  ers = sm + 41472;                  // [16][32]                  2048 B
    float*  wrs = sm + 41984;                  // [16]                        64 B

    const int b = blockIdx.y, vt = blockIdx.x;
    const int tid = threadIdx.x, w = tid >> 5, lane = tid & 31;
    const int v = vt*32 + lane;
    const float c0 = coeffs[0], c1 = coeffs[1], c2 = coeffs[2];
    const float f0 = 0.125f*c0, f1 = 0.125f*c1, f2 = 0.125f*c2;

    float* Mb = g_M + (size_t)b*DP*D;
    float* Sb = g_S + (size_t)b*DP*D;
    float s_prev = 1.0f;   // M0 = 0 -> first clip scale is 1

    for (int n=0;n<NCH;n++){
        // ---- stage k,q chunk tables into smem ----
        const float* Kc = g_K + ((size_t)b*SEQ + n*CWIN)*D;
        const float* Qc = g_Q + ((size_t)b*SEQ + n*CWIN)*D;
        #pragma unroll
        for (int idx=tid; idx<8192; idx+=512){
            int c = idx >> 9, j = idx & 511;
            float kv = Kc[(size_t)c*D + j];
            float qv = Qc[(size_t)c*D + j];
            ks2[c*512 + j] = make_float2(kv, kv*kv);
            qs2[c*512 + j] = make_float2(c1*qv, c2*qv*qv);
        }
        __syncthreads();

        // ---- phase A: pred partials (warp w covers j = w + 16t) ----
        float acc[16];
        #pragma unroll
        for (int c=0;c<16;c++) acc[c]=0.f;
        float r0 = 0.f;
        #pragma unroll 2
        for (int t=0;t<32;t++){
            int j = w + t*16;
            float m0 = Mb[(size_t)j*D + v];
            float m1 = Mb[(size_t)(512 + j)*D + v];
            float m2 = Mb[(size_t)(1024 + j)*D + v];
            r0 += m0;
            float t1 = c1*m1, t2 = c2*m2;
            #pragma unroll
            for (int c=0;c<16;c++){
                float kk = ks2[c*512 + j].x;
                acc[c] = fmaf(kk, fmaf(kk, t2, t1), acc[c]);
            }
        }
        #pragma unroll
        for (int c=0;c<16;c++) red[(w*16 + c)*32 + lane] = acc[c];
        r0r[w*32 + lane] = r0;
        __syncthreads();

        // warp w reduces output row c = w, computes err
        {
            float R0=0.f, p=0.f;
            #pragma unroll
            for (int ww=0;ww<16;ww++){
                R0 += r0r[ww*32 + lane];
                p  += red[(ww*16 + w)*32 + lane];
            }
            p = fmaf(c0, R0, p) * s_prev;
            float vv = g_V[((size_t)b*SEQ + n*CWIN + w)*D + v];
            float e = g_gamma[(b*NCH + n)*CWIN + w] * (p - vv);
            ers[w*32 + lane] = e;
        }
        __syncthreads();

        float e_[16];
        #pragma unroll
        for (int c=0;c<16;c++) e_[c] = ers[c*32 + lane];
        float g0 = 0.f;
        #pragma unroll
        for (int c=0;c<16;c++) g0 += e_[c];
        g0 *= f0;

        int gi = b*NCH + n;
        float al = g_alpha[gi]*s_prev, th = g_theta[gi], et = g_eta[gi];

        // ---- phase B: grad + S/M update + fused y accumulation + sumsq ----
        float yacc[16];
        #pragma unroll
        for (int c=0;c<16;c++) yacc[c]=0.f;
        float y0 = 0.f, sq = 0.f;

        #pragma unroll 2
        for (int t=0;t<32;t++){
            int j = w + t*16;
            size_t i0 = (size_t)j*D + v;
            size_t i1 = i0 + (size_t)512*D;
            size_t i2 = i0 + (size_t)1024*D;
            float mo0 = Mb[i0], so0 = Sb[i0];
            float mo1 = Mb[i1], so1 = Sb[i1];
            float mo2 = Mb[i2], so2 = Sb[i2];
            float g1 = 0.f, g2 = 0.f;
            #pragma unroll
            for (int c=0;c<16;c++){
                float2 kk = ks2[c*512 + j];
                g1 = fmaf(kk.x, e_[c], g1);
                g2 = fmaf(kk.y, e_[c], g2);
            }
            float sn0 = th*so0 - et*g0;
            float sn1 = th*so1 - et*(f1*g1);
            float sn2 = th*so2 - et*(f2*g2);
            float mn0 = fmaf(al, mo0, sn0);
            float mn1 = fmaf(al, mo1, sn1);
            float mn2 = fmaf(al, mo2, sn2);
            Sb[i0]=sn0; Sb[i1]=sn1; Sb[i2]=sn2;
            Mb[i0]=mn0; Mb[i1]=mn1; Mb[i2]=mn2;
            y0 += mn0;
            sq = fmaf(mn0,mn0, sq); sq = fmaf(mn1,mn1, sq); sq = fmaf(mn2,mn2, sq);
            #pragma unroll
            for (int c=0;c<16;c++){
                float2 qq = qs2[c*512 + j];
                yacc[c] = fmaf(qq.x, mn1, fmaf(qq.y, mn2, yacc[c]));
            }
        }

        // ---- y reduction (reuse red/r0r; safe: prior reads completed pre-sync) ----
        #pragma unroll
        for (int c=0;c<16;c++) red[(w*16 + c)*32 + lane] = yacc[c];
        r0r[w*32 + lane] = y0;
        float sqw = wred(sq);
        if (lane==0) wrs[w] = sqw;
        __syncthreads();

        float Y0=0.f, yv=0.f;
        #pragma unroll
        for (int ww=0;ww<16;ww++){
            Y0 += r0r[ww*32 + lane];
            yv += red[(ww*16 + w)*32 + lane];
        }
        yv = fmaf(c0, Y0, yv);

        // ---- per-batch barrier: publish sumsq partial, wait for all 16 stripes ----
        if (tid==0){
            float tot=0.f;
            #pragma unroll
            for (int i=0;i<16;i++) tot += wrs[i];
            g_part2[b*16 + vt] = tot;
            __threadfence();
            atomicAdd(&g_ctr[b], 1u);
            unsigned int target = 16u*(unsigned)(n+1);
            while (atomicAdd(&g_ctr[b], 0u) < target) __nanosleep(64);
        }
        __syncthreads();
        __threadfence();

        float ss=0.f;
        #pragma unroll
        for (int i=0;i<16;i++) ss += __ldcg(&g_part2[b*16 + i]);
        float s_n = fminf(50.0f/(sqrtf(ss) + 1e-6f), 1.0f);

        g_Y[((size_t)b*SEQ + n*CWIN + w)*D + v] = s_n * yv;
        s_prev = s_n;
    }
}

// ---------------- launch ----------------
extern "C" void kernel_launch(void* const* d_in, const int* in_sizes, int n_in,
                              void* d_out, int out_size)
{
    const float* x     = (const float*)d_in[0];
    const float* M0    = (const float*)d_in[1];
    const float* S0    = (const float*)d_in[2];
    const float* Wk    = (const float*)d_in[3];
    const float* Wv    = (const float*)d_in[4];
    const float* Wq    = (const float*)d_in[5];
    const float* Wqk   = (const float*)d_in[6];
    const float* Wout  = (const float*)d_in[7];
    const float* coeffs= (const float*)d_in[8];
    const float* cgWq  = (const float*)d_in[9];
    const float* cgWk  = (const float*)d_in[10];
    const float* temp  = (const float*)d_in[11];
    const float* aw    = (const float*)d_in[12];
    const float* ab    = (const float*)d_in[13];
    const float* tw    = (const float*)d_in[14];
    const float* tb    = (const float*)d_in[15];
    const float* ew    = (const float*)d_in[16];
    const float* eb    = (const float*)d_in[17];
    float* out = (float*)d_out;

    float *pM,*pS,*pK,*pV,*pQ,*pY,*pE,*pXl,*pQG,*pT;
    cudaGetSymbolAddress((void**)&pM,  g_M);
    cudaGetSymbolAddress((void**)&pS,  g_S);
    cudaGetSymbolAddress((void**)&pK,  g_K);
    cudaGetSymbolAddress((void**)&pV,  g_V);
    cudaGetSymbolAddress((void**)&pQ,  g_Q);
    cudaGetSymbolAddress((void**)&pY,  g_Y);
    cudaGetSymbolAddress((void**)&pE,  g_E);
    cudaGetSymbolAddress((void**)&pXl, g_Xlast);
    cudaGetSymbolAddress((void**)&pQG, g_QG);
    cudaGetSymbolAddress((void**)&pT,  g_T);

    static int smem_set = 0;
    if (!smem_set){
        cudaFuncSetAttribute(chunk_loop_kernel,
                             cudaFuncAttributeMaxDynamicSharedMemorySize, 168064);
        smem_set = 1;
    }

    cudaMemcpyAsync(pM, M0, sizeof(float)*(size_t)BB*DP*D, cudaMemcpyDeviceToDevice);
    cudaMemcpyAsync(pS, S0, sizeof(float)*(size_t)BB*DP*D, cudaMemcpyDeviceToDevice);
    zero_ctrs<<<1,256>>>();

    // fold Wqk@Wq, then the big projections
    gemm_kernel<false><<<dim3(4,4),  256>>>(Wqk, Wq,  pE, 512,   512, 512);
    gemm_kernel<true ><<<dim3(4,128),256>>>(x,   Wk,  pK, BB*SEQ,512, 512);
    gemm_kernel<true ><<<dim3(4,128),256>>>(x,   Wv,  pV, BB*SEQ,512, 512);
    gemm_kernel<true ><<<dim3(4,128),256>>>(x,   pE,  pQ, BB*SEQ,512, 512);

    // gates
    gather_xlast<<<2048,256>>>(x);
    gemm_kernel<true ><<<dim3(4,8),256>>>(pXl, cgWq, pQG, BB*NCH, 512, 512);
    gemm_kernel<false><<<dim3(4,8),256>>>(pQG, cgWk, pT,  BB*NCH, 512, 512);
    gates_kernel<<<BB*NCH,128>>>(x, temp, aw, ab, tw, tb, ew, eb);

    // entire 128-chunk recurrence in ONE persistent kernel
    chunk_loop_kernel<<<dim3(16,8),512,168064>>>(coeffs);

    // out = Y @ Wout^T
    gemm_kernel<true><<<dim3(4,128),256>>>(pY, Wout, out, BB*SEQ, 512, 512);
}

// round 4
// speedup vs baseline: 2.2762x; 1.2474x over previous
#include <cuda_runtime.h>
#include <math.h>

#define BB   8
#define SEQ  2048
#define D    512
#define CWIN 16
#define NCH  128
#define DP   1536

typedef unsigned long long u64;

// ---------------- persistent device scratch ----------------
__device__ float g_K[BB*SEQ*D];
__device__ float g_V[BB*SEQ*D];
__device__ float g_Q[BB*SEQ*D];
__device__ float g_Y[BB*SEQ*D];
__device__ float g_M[(size_t)BB*DP*D];
__device__ float g_S[(size_t)BB*DP*D];
__device__ float g_E[D*D];
__device__ float g_Xlast[BB*NCH*D];
__device__ float g_QG[BB*NCH*D];
__device__ float g_T[BB*NCH*D];
__device__ float g_gamma[BB*NCH*CWIN];
__device__ float g_alpha[BB*NCH];
__device__ float g_theta[BB*NCH];
__device__ float g_eta[BB*NCH];
__device__ float g_part2[2*BB*16];
__device__ unsigned int g_ctr[BB];

// ---------------- f32x2 packed helpers (sm_100+) ----------------
__device__ __forceinline__ u64 PK2(float lo, float hi){
    u64 r; asm("mov.b64 %0, {%1,%2};" : "=l"(r) : "f"(lo), "f"(hi)); return r;
}
__device__ __forceinline__ void UNPK(u64 v, float& a, float& b){
    asm("mov.b64 {%0,%1}, %2;" : "=f"(a), "=f"(b) : "l"(v));
}
__device__ __forceinline__ u64 FMA2(u64 a, u64 b, u64 c){
    u64 d; asm("fma.rn.f32x2 %0,%1,%2,%3;" : "=l"(d) : "l"(a), "l"(b), "l"(c)); return d;
}
__device__ __forceinline__ u64 MUL2(u64 a, u64 b){
    u64 d; asm("mul.rn.f32x2 %0,%1,%2;" : "=l"(d) : "l"(a), "l"(b)); return d;
}
__device__ __forceinline__ u64 ADD2(u64 a, u64 b){
    u64 d; asm("add.rn.f32x2 %0,%1,%2;" : "=l"(d) : "l"(a), "l"(b)); return d;
}

__device__ __forceinline__ float wred(float x){
    #pragma unroll
    for (int o=16;o;o>>=1) x += __shfl_down_sync(0xffffffffu, x, o);
    return x;
}

// ---------------- generic fp32 GEMM ----------------
template<bool NT>
__global__ void __launch_bounds__(256) gemm_kernel(const float* __restrict__ A,
                                                   const float* __restrict__ Bm,
                                                   float* __restrict__ Cm,
                                                   int M, int N, int K)
{
    __shared__ float As[16][132];
    __shared__ float Bs[16][132];
    int tid = threadIdx.x;
    int m0 = blockIdx.y * 128, n0 = blockIdx.x * 128;
    int ty = tid >> 4, tx = tid & 15;
    float acc[8][8];
    #pragma unroll
    for (int i=0;i<8;i++)
        #pragma unroll
        for (int j=0;j<8;j++) acc[i][j]=0.f;

    for (int k0=0;k0<K;k0+=16){
        #pragma unroll
        for (int l=0;l<2;l++){
            int idx = tid + l*256;
            int row = idx >> 2, k4 = (idx & 3)*4;
            float4 av = *(const float4*)(A + (size_t)(m0+row)*K + k0 + k4);
            As[k4+0][row]=av.x; As[k4+1][row]=av.y; As[k4+2][row]=av.z; As[k4+3][row]=av.w;
        }
        if (NT){
            #pragma unroll
            for (int l=0;l<2;l++){
                int idx = tid + l*256;
                int row = idx >> 2, k4 = (idx & 3)*4;
                float4 bv = *(const float4*)(Bm + (size_t)(n0+row)*K + k0 + k4);
                Bs[k4+0][row]=bv.x; Bs[k4+1][row]=bv.y; Bs[k4+2][row]=bv.z; Bs[k4+3][row]=bv.w;
            }
        } else {
            #pragma unroll
            for (int l=0;l<2;l++){
                int idx = tid + l*256;
                int kr = idx >> 5, n4 = (idx & 31)*4;
                float4 bv = *(const float4*)(Bm + (size_t)(k0+kr)*N + n0 + n4);
                *(float4*)&Bs[kr][n4] = bv;
            }
        }
        __syncthreads();
        #pragma unroll
        for (int kk=0;kk<16;kk++){
            float a[8], b[8];
            *(float4*)(a)   = *(const float4*)&As[kk][ty*8];
            *(float4*)(a+4) = *(const float4*)&As[kk][ty*8+4];
            *(float4*)(b)   = *(const float4*)&Bs[kk][tx*8];
            *(float4*)(b+4) = *(const float4*)&Bs[kk][tx*8+4];
            #pragma unroll
            for (int i=0;i<8;i++)
                #pragma unroll
                for (int j=0;j<8;j++) acc[i][j] = fmaf(a[i], b[j], acc[i][j]);
        }
        __syncthreads();
    }
    #pragma unroll
    for (int i=0;i<8;i++){
        size_t r = (size_t)(m0 + ty*8 + i)*N + n0 + tx*8;
        *(float4*)(Cm + r)     = make_float4(acc[i][0],acc[i][1],acc[i][2],acc[i][3]);
        *(float4*)(Cm + r + 4) = make_float4(acc[i][4],acc[i][5],acc[i][6],acc[i][7]);
    }
}

// ---------------- gather last token of each chunk ----------------
__global__ void gather_xlast(const float* __restrict__ x){
    int i = blockIdx.x*256 + threadIdx.x;
    if (i < BB*NCH*D){
        int e = i & 511; int r = i >> 9; int b = r >> 7; int n = r & 127;
        g_Xlast[i] = x[((size_t)b*SEQ + n*CWIN + (CWIN-1))*D + e];
    }
}

__global__ void zero_ctrs(){
    int i = threadIdx.x;
    if (i < BB) g_ctr[i] = 0u;
}

// ---------------- gates ----------------
__global__ void __launch_bounds__(128) gates_kernel(const float* __restrict__ x,
    const float* __restrict__ temp,
    const float* __restrict__ aw, const float* __restrict__ ab,
    const float* __restrict__ tw, const float* __restrict__ tb,
    const float* __restrict__ ew, const float* __restrict__ eb)
{
    int r = blockIdx.x; int b = r >> 7; int n = r & 127;
    int tid = threadIdx.x, w = tid >> 5, lane = tid & 31;
    __shared__ float ts[512];
    __shared__ float accA[16], accT[16], accE[16];
    for (int i=tid;i<512;i+=128) ts[i] = g_T[(size_t)r*512 + i];
    __syncthreads();
    float invt = 1.0f/(22.627416997969522f * fmaxf(temp[0], 0.1f));
    for (int c=w;c<16;c+=4){
        const float* xr = x + ((size_t)b*SEQ + n*CWIN + c)*D;
        float gs=0.f, as=0.f, tws=0.f, es=0.f;
        for (int e=lane;e<512;e+=32){
            float xv = xr[e];
            gs  = fmaf(xv, ts[e], gs);
            as  = fmaf(xv, aw[e], as);
            tws = fmaf(xv, tw[e], tws);
            es  = fmaf(xv, ew[e], es);
        }
        gs = wred(gs); as = wred(as); tws = wred(tws); es = wred(es);
        if (lane==0){
            g_gamma[(size_t)r*CWIN + c] = 1.f/(1.f + expf(-gs*invt));
            accA[c]=as; accT[c]=tws; accE[c]=es;
        }
    }
    __syncthreads();
    if (tid==0){
        float sa=0.f, st=0.f, se=0.f;
        for (int c=0;c<16;c++){ sa+=accA[c]; st+=accT[c]; se+=accE[c]; }
        sa = sa*(1.f/16.f) + ab[0];
        st = st*(1.f/16.f) + tb[0];
        se = se*(1.f/16.f) + eb[0];
        g_alpha[r] = 1.f/(1.f+expf(-sa));
        g_theta[r] = 1.f/(1.f+expf(-st));
        g_eta[r]   = 1.f/(1.f+expf(-se));
    }
}

// ---------------- persistent chunk-recurrence kernel (f32x2) ----------------
// grid (16,8): block (vt,b) owns columns [vt*32, vt*32+32) of M,S for batch b.
// Each thread: column pair pi (tid&15), j-group jg (tid>>4), j = jg + 32t.
// Norm barrier is published right after the update and awaited only before the
// NEXT chunk's err computation (hidden behind staging + pred phase).
#define SM_KS   0           // u64[16*512]  splat (k,k)            65536 B
#define SM_QS   65536       // u64[16*512*2] splat q pairs        131072 B (aliased by RED)
#define SM_R0R  196608      // u64[32*16]                           4096 B
#define SM_ERS  200704      // u64[16*16]                           2048 B
#define SM_WRS  202752      // float[16]
#define SM_SBC  202816      // float[1]
#define SM_TOT  202880

__global__ void __launch_bounds__(512) chunk_loop_kernel(const float* __restrict__ coeffs)
{
    extern __shared__ char smraw[];
    u64*   KS  = (u64*)(smraw + SM_KS);
    u64*   QS  = (u64*)(smraw + SM_QS);
    u64*   RED = (u64*)(smraw + SM_QS);    // alias [32][16][16]
    u64*   R0R = (u64*)(smraw + SM_R0R);
    u64*   ERS = (u64*)(smraw + SM_ERS);
    float* WRS = (float*)(smraw + SM_WRS);
    float* SBC = (float*)(smraw + SM_SBC);

    const int b = blockIdx.y, vt = blockIdx.x;
    const int tid = threadIdx.x;
    const int pi = tid & 15, jg = tid >> 4;
    const int w = tid >> 5, lane = tid & 31;
    const int v0 = vt*32 + 2*pi;
    const int rc = tid >> 4, rpi = tid & 15;   // reduce roles (tid<256)

    const float c0 = coeffs[0], c1 = coeffs[1], c2 = coeffs[2];
    const u64 c0_2 = PK2(c0,c0), c1_2 = PK2(c1,c1), c2_2 = PK2(c2,c2);
    const float f0 = 0.125f*c0, f1 = 0.125f*c1, f2 = 0.125f*c2;

    float* Mb = g_M + (size_t)b*DP*D;
    float* Sb = g_S + (size_t)b*DP*D;

    u64 yv_pend = 0ull;

    for (int n=0;n<NCH;n++){
        // ---- stage k (splatted) ----
        const float* Kc = g_K + ((size_t)b*SEQ + n*CWIN)*D;
        #pragma unroll
        for (int i=0;i<16;i++){
            int idx = tid + i*512;
            float kv = Kc[idx];
            KS[idx] = PK2(kv,kv);
        }
        __syncthreads();

        // ---- phase A: pred partials ----
        u64 acc[16];
        #pragma unroll
        for (int c=0;c<16;c++) acc[c]=0ull;
        u64 r0 = 0ull;
        const float* pA = Mb + (size_t)jg*D + v0;
        #pragma unroll 2
        for (int t=0;t<16;t++){
            u64 m0 = *(const u64*)(pA);
            u64 m1 = *(const u64*)(pA + 512*D);
            u64 m2 = *(const u64*)(pA + 1024*D);
            pA += 32*D;
            r0 = ADD2(r0, m0);
            u64 t1 = MUL2(c1_2, m1), t2 = MUL2(c2_2, m2);
            int j = jg + 32*t;
            #pragma unroll
            for (int c=0;c<16;c++){
                u64 kk = KS[c*512 + j];
                acc[c] = FMA2(kk, FMA2(kk, t2, t1), acc[c]);
            }
        }
        #pragma unroll
        for (int c=0;c<16;c++) RED[(jg*16 + c)*16 + pi] = acc[c];
        R0R[jg*16 + pi] = r0;
        __syncthreads();

        // ---- pred reduce (tid<256) ----
        u64 p2 = 0ull;
        if (tid < 256){
            u64 ps = 0ull, r0s = 0ull;
            #pragma unroll
            for (int g=0;g<32;g++){
                ps  = ADD2(ps,  RED[(g*16 + rc)*16 + rpi]);
                r0s = ADD2(r0s, R0R[g*16 + rpi]);
            }
            p2 = FMA2(c0_2, r0s, ps);
        }

        // ---- wait for chunk n-1 norm (overlapped) ----
        if (tid==0 && n>0){
            unsigned target = 16u*(unsigned)n;
            while (atomicAdd(&g_ctr[b], 0u) < target) __nanosleep(32);
            __threadfence();
            float ss = 0.f;
            const float* pp = g_part2 + ((n-1)&1)*BB*16 + b*16;
            #pragma unroll
            for (int i=0;i<16;i++) ss += __ldcg(&pp[i]);
            SBC[0] = fminf(50.0f/(sqrtf(ss)+1e-6f), 1.0f);
        }
        __syncthreads();
        float s_prev = (n>0) ? SBC[0] : 1.0f;

        // ---- write pending y(n-1), compute err(n); all threads stage q ----
        if (tid < 256){
            if (n>0){
                float ya,yb; UNPK(yv_pend, ya, yb);
                *(float2*)&g_Y[((size_t)b*SEQ + (n-1)*CWIN + rc)*D + vt*32 + 2*rpi]
                    = make_float2(s_prev*ya, s_prev*yb);
            }
            float pa,pb; UNPK(p2, pa, pb);
            const float* Vp = g_V + ((size_t)b*SEQ + n*CWIN + rc)*D + vt*32 + 2*rpi;
            float ga = g_gamma[(b*NCH + n)*CWIN + rc];
            float ea = ga*(pa*s_prev - Vp[0]);
            float eb = ga*(pb*s_prev - Vp[1]);
            ERS[rc*16 + rpi] = PK2(ea, eb);
        }
        {
            const float* Qc = g_Q + ((size_t)b*SEQ + n*CWIN)*D;
            #pragma unroll
            for (int i=0;i<16;i++){
                int idx = tid + i*512;
                float qv = Qc[idx];
                float a = c1*qv, bq = c2*qv*qv;
                QS[idx*2+0] = PK2(a,a);
                QS[idx*2+1] = PK2(bq,bq);
            }
        }
        __syncthreads();

        // ---- phase B: grad + update + fused y + sumsq ----
        u64 e2[16];
        #pragma unroll
        for (int c=0;c<16;c++) e2[c] = ERS[c*16 + pi];
        u64 g0 = 0ull;
        #pragma unroll
        for (int c=0;c<16;c++) g0 = ADD2(g0, e2[c]);

        int gi = b*NCH + n;
        float alf = g_alpha[gi]*s_prev, thf = g_theta[gi], etf = g_eta[gi];
        u64 al = PK2(alf,alf), th = PK2(thf,thf);
        u64 nf0 = PK2(-etf*f0, -etf*f0);
        u64 nf1 = PK2(-etf*f1, -etf*f1);
        u64 nf2 = PK2(-etf*f2, -etf*f2);
        u64 t0term = MUL2(g0, nf0);

        u64 yacc[16];
        #pragma unroll
        for (int c=0;c<16;c++) yacc[c]=0ull;
        u64 y0 = 0ull, sq2 = 0ull;

        float* pM = Mb + (size_t)jg*D + v0;
        float* pS = Sb + (size_t)jg*D + v0;
        #pragma unroll 1
        for (int t=0;t<16;t++){
            int j = jg + 32*t;
            u64 mo0 = *(const u64*)(pM);
            u64 mo1 = *(const u64*)(pM + 512*D);
            u64 mo2 = *(const u64*)(pM + 1024*D);
            u64 so0 = *(const u64*)(pS);
            u64 so1 = *(const u64*)(pS + 512*D);
            u64 so2 = *(const u64*)(pS + 1024*D);
            u64 g1 = 0ull, g2 = 0ull;
            #pragma unroll
            for (int c=0;c<16;c++){
                u64 kk = KS[c*512 + j];
                u64 kk2 = MUL2(kk,kk);
                g1 = FMA2(kk,  e2[c], g1);
                g2 = FMA2(kk2, e2[c], g2);
            }
            u64 sn0 = FMA2(th, so0, t0term);
            u64 sn1 = FMA2(nf1, g1, MUL2(th, so1));
            u64 sn2 = FMA2(nf2, g2, MUL2(th, so2));
            u64 mn0 = FMA2(al, mo0, sn0);
            u64 mn1 = FMA2(al, mo1, sn1);
            u64 mn2 = FMA2(al, mo2, sn2);
            *(u64*)(pS)          = sn0;
            *(u64*)(pS + 512*D)  = sn1;
            *(u64*)(pS + 1024*D) = sn2;
            *(u64*)(pM)          = mn0;
            *(u64*)(pM + 512*D)  = mn1;
            *(u64*)(pM + 1024*D) = mn2;
            pM += 32*D; pS += 32*D;
            y0  = ADD2(y0, mn0);
            sq2 = FMA2(mn0,mn0,sq2); sq2 = FMA2(mn1,mn1,sq2); sq2 = FMA2(mn2,mn2,sq2);
            #pragma unroll
            for (int c=0;c<16;c++){
                ulonglong2 qq = *(const ulonglong2*)&QS[(c*512 + j)*2];
                yacc[c] = FMA2(qq.x, mn1, FMA2(qq.y, mn2, yacc[c]));
            }
        }
        float sa,sb; UNPK(sq2, sa, sb);
        float sq = wred(sa + sb);
        if (lane==0) WRS[w] = sq;
        __syncthreads();                       // all t-loops done -> QS dead

        #pragma unroll
        for (int c=0;c<16;c++) RED[(jg*16 + c)*16 + pi] = yacc[c];
        R0R[jg*16 + pi] = y0;
        __syncthreads();

        if (tid < 256){
            u64 ys = 0ull, y0s = 0ull;
            #pragma unroll
            for (int g=0;g<32;g++){
                ys  = ADD2(ys,  RED[(g*16 + rc)*16 + rpi]);
                y0s = ADD2(y0s, R0R[g*16 + rpi]);
            }
            yv_pend = FMA2(c0_2, y0s, ys);
        }
        if (tid==0){
            float tot = 0.f;
            #pragma unroll
            for (int i=0;i<16;i++) tot += WRS[i];
            g_part2[(n&1)*BB*16 + b*16 + vt] = tot;
            __threadfence();
            atomicAdd(&g_ctr[b], 1u);
        }
        __syncthreads();
    }

    // ---- tail: y for chunk 127 ----
    if (tid==0){
        unsigned target = 16u*NCH;
        while (atomicAdd(&g_ctr[b], 0u) < target) __nanosleep(32);
        __threadfence();
        float ss = 0.f;
        const float* pp = g_part2 + ((NCH-1)&1)*BB*16 + b*16;
        #pragma unroll
        for (int i=0;i<16;i++) ss += __ldcg(&pp[i]);
        SBC[0] = fminf(50.0f/(sqrtf(ss)+1e-6f), 1.0f);
    }
    __syncthreads();
    if (tid < 256){
        float s = SBC[0];
        float ya,yb; UNPK(yv_pend, ya, yb);
        *(float2*)&g_Y[((size_t)b*SEQ + (NCH-1)*CWIN + rc)*D + vt*32 + 2*rpi]
            = make_float2(s*ya, s*yb);
    }
}

// ---------------- launch ----------------
extern "C" void kernel_launch(void* const* d_in, const int* in_sizes, int n_in,
                              void* d_out, int out_size)
{
    const float* x     = (const float*)d_in[0];
    const float* M0    = (const float*)d_in[1];
    const float* S0    = (const float*)d_in[2];
    const float* Wk    = (const float*)d_in[3];
    const float* Wv    = (const float*)d_in[4];
    const float* Wq    = (const float*)d_in[5];
    const float* Wqk   = (const float*)d_in[6];
    const float* Wout  = (const float*)d_in[7];
    const float* coeffs= (const float*)d_in[8];
    const float* cgWq  = (const float*)d_in[9];
    const float* cgWk  = (const float*)d_in[10];
    const float* temp  = (const float*)d_in[11];
    const float* aw    = (const float*)d_in[12];
    const float* ab    = (const float*)d_in[13];
    const float* tw    = (const float*)d_in[14];
    const float* tb    = (const float*)d_in[15];
    const float* ew    = (const float*)d_in[16];
    const float* eb    = (const float*)d_in[17];
    float* out = (float*)d_out;

    float *pM,*pS,*pK,*pV,*pQ,*pY,*pE,*pXl,*pQG,*pT;
    cudaGetSymbolAddress((void**)&pM,  g_M);
    cudaGetSymbolAddress((void**)&pS,  g_S);
    cudaGetSymbolAddress((void**)&pK,  g_K);
    cudaGetSymbolAddress((void**)&pV,  g_V);
    cudaGetSymbolAddress((void**)&pQ,  g_Q);
    cudaGetSymbolAddress((void**)&pY,  g_Y);
    cudaGetSymbolAddress((void**)&pE,  g_E);
    cudaGetSymbolAddress((void**)&pXl, g_Xlast);
    cudaGetSymbolAddress((void**)&pQG, g_QG);
    cudaGetSymbolAddress((void**)&pT,  g_T);

    cudaFuncSetAttribute(chunk_loop_kernel,
                         cudaFuncAttributeMaxDynamicSharedMemorySize, SM_TOT);

    cudaMemcpyAsync(pM, M0, sizeof(float)*(size_t)BB*DP*D, cudaMemcpyDeviceToDevice);
    cudaMemcpyAsync(pS, S0, sizeof(float)*(size_t)BB*DP*D, cudaMemcpyDeviceToDevice);
    zero_ctrs<<<1,32>>>();

    // fold Wqk@Wq, then the big projections
    gemm_kernel<false><<<dim3(4,4),  256>>>(Wqk, Wq,  pE, 512,   512, 512);
    gemm_kernel<true ><<<dim3(4,128),256>>>(x,   Wk,  pK, BB*SEQ,512, 512);
    gemm_kernel<true ><<<dim3(4,128),256>>>(x,   Wv,  pV, BB*SEQ,512, 512);
    gemm_kernel<true ><<<dim3(4,128),256>>>(x,   pE,  pQ, BB*SEQ,512, 512);

    // gates
    gather_xlast<<<2048,256>>>(x);
    gemm_kernel<true ><<<dim3(4,8),256>>>(pXl, cgWq, pQG, BB*NCH, 512, 512);
    gemm_kernel<false><<<dim3(4,8),256>>>(pQG, cgWk, pT,  BB*NCH, 512, 512);
    gates_kernel<<<BB*NCH,128>>>(x, temp, aw, ab, tw, tb, ew, eb);

    // entire 128-chunk recurrence in ONE persistent kernel
    chunk_loop_kernel<<<dim3(16,8),512,SM_TOT>>>(coeffs);

    // out = Y @ Wout^T
    gemm_kernel<true><<<dim3(4,128),256>>>(pY, Wout, out, BB*SEQ, 512, 512);
}

// round 5
// speedup vs baseline: 2.3707x; 1.0415x over previous
#include <cuda_runtime.h>
#include <math.h>

#define BB   8
#define SEQ  2048
#define D    512
#define CWIN 16
#define NCH  128
#define DP   1536

typedef unsigned long long u64;

// ---------------- persistent device scratch ----------------
__device__ float g_K[BB*SEQ*D];
__device__ float g_V[BB*SEQ*D];
__device__ float g_Q[BB*SEQ*D];
__device__ float g_Y[BB*SEQ*D];
__device__ float g_M[(size_t)BB*DP*D];
__device__ float g_S[(size_t)BB*DP*D];
__device__ float g_E[D*D];
__device__ float g_Xlast[BB*NCH*D];
__device__ float g_QG[BB*NCH*D];
__device__ float g_T[BB*NCH*D];
__device__ float g_gamma[BB*NCH*CWIN];
__device__ float g_alpha[BB*NCH];
__device__ float g_theta[BB*NCH];
__device__ float g_eta[BB*NCH];
__device__ float g_part2[2*BB*16];
__device__ unsigned int g_ctr[BB];

// ---------------- f32x2 packed helpers (sm_100+) ----------------
__device__ __forceinline__ u64 PK2(float lo, float hi){
    u64 r; asm("mov.b64 %0, {%1,%2};" : "=l"(r) : "f"(lo), "f"(hi)); return r;
}
__device__ __forceinline__ void UNPK(u64 v, float& a, float& b){
    asm("mov.b64 {%0,%1}, %2;" : "=f"(a), "=f"(b) : "l"(v));
}
__device__ __forceinline__ u64 FMA2(u64 a, u64 b, u64 c){
    u64 d; asm("fma.rn.f32x2 %0,%1,%2,%3;" : "=l"(d) : "l"(a), "l"(b), "l"(c)); return d;
}
__device__ __forceinline__ u64 MUL2(u64 a, u64 b){
    u64 d; asm("mul.rn.f32x2 %0,%1,%2;" : "=l"(d) : "l"(a), "l"(b)); return d;
}
__device__ __forceinline__ u64 ADD2(u64 a, u64 b){
    u64 d; asm("add.rn.f32x2 %0,%1,%2;" : "=l"(d) : "l"(a), "l"(b)); return d;
}

__device__ __forceinline__ float wred(float x){
    #pragma unroll
    for (int o=16;o;o>>=1) x += __shfl_down_sync(0xffffffffu, x, o);
    return x;
}

// ---------------- generic fp32 GEMM (f32x2 inner product) ----------------
template<bool NT>
__global__ void __launch_bounds__(256) gemm_kernel(const float* __restrict__ A,
                                                   const float* __restrict__ Bm,
                                                   float* __restrict__ Cm,
                                                   int M, int N, int K)
{
    __shared__ float As[16][132];
    __shared__ float Bs[16][132];
    int tid = threadIdx.x;
    int m0 = blockIdx.y * 128, n0 = blockIdx.x * 128;
    int ty = tid >> 4, tx = tid & 15;
    u64 acc2[8][4];
    #pragma unroll
    for (int i=0;i<8;i++)
        #pragma unroll
        for (int j=0;j<4;j++) acc2[i][j]=0ull;

    for (int k0=0;k0<K;k0+=16){
        #pragma unroll
        for (int l=0;l<2;l++){
            int idx = tid + l*256;
            int row = idx >> 2, k4 = (idx & 3)*4;
            float4 av = *(const float4*)(A + (size_t)(m0+row)*K + k0 + k4);
            As[k4+0][row]=av.x; As[k4+1][row]=av.y; As[k4+2][row]=av.z; As[k4+3][row]=av.w;
        }
        if (NT){
            #pragma unroll
            for (int l=0;l<2;l++){
                int idx = tid + l*256;
                int row = idx >> 2, k4 = (idx & 3)*4;
                float4 bv = *(const float4*)(Bm + (size_t)(n0+row)*K + k0 + k4);
                Bs[k4+0][row]=bv.x; Bs[k4+1][row]=bv.y; Bs[k4+2][row]=bv.z; Bs[k4+3][row]=bv.w;
            }
        } else {
            #pragma unroll
            for (int l=0;l<2;l++){
                int idx = tid + l*256;
                int kr = idx >> 5, n4 = (idx & 31)*4;
                float4 bv = *(const float4*)(Bm + (size_t)(k0+kr)*N + n0 + n4);
                *(float4*)&Bs[kr][n4] = bv;
            }
        }
        __syncthreads();
        #pragma unroll
        for (int kk=0;kk<16;kk++){
            float a[8];
            *(float4*)(a)   = *(const float4*)&As[kk][ty*8];
            *(float4*)(a+4) = *(const float4*)&As[kk][ty*8+4];
            u64 b2[4];
            *(ulonglong2*)&b2[0] = *(const ulonglong2*)&Bs[kk][tx*8];
            *(ulonglong2*)&b2[2] = *(const ulonglong2*)&Bs[kk][tx*8+4];
            #pragma unroll
            for (int i=0;i<8;i++){
                u64 ai = PK2(a[i], a[i]);
                #pragma unroll
                for (int jp=0;jp<4;jp++) acc2[i][jp] = FMA2(ai, b2[jp], acc2[i][jp]);
            }
        }
        __syncthreads();
    }
    #pragma unroll
    for (int i=0;i<8;i++){
        float o[8];
        #pragma unroll
        for (int jp=0;jp<4;jp++) UNPK(acc2[i][jp], o[2*jp], o[2*jp+1]);
        size_t r = (size_t)(m0 + ty*8 + i)*N + n0 + tx*8;
        *(float4*)(Cm + r)     = make_float4(o[0],o[1],o[2],o[3]);
        *(float4*)(Cm + r + 4) = make_float4(o[4],o[5],o[6],o[7]);
    }
}

// ---------------- gather last token of each chunk ----------------
__global__ void gather_xlast(const float* __restrict__ x){
    int i = blockIdx.x*256 + threadIdx.x;
    if (i < BB*NCH*D){
        int e = i & 511; int r = i >> 9; int b = r >> 7; int n = r & 127;
        g_Xlast[i] = x[((size_t)b*SEQ + n*CWIN + (CWIN-1))*D + e];
    }
}

__global__ void zero_ctrs(){
    int i = threadIdx.x;
    if (i < BB) g_ctr[i] = 0u;
}

// ---------------- gates ----------------
__global__ void __launch_bounds__(128) gates_kernel(const float* __restrict__ x,
    const float* __restrict__ temp,
    const float* __restrict__ aw, const float* __restrict__ ab,
    const float* __restrict__ tw, const float* __restrict__ tb,
    const float* __restrict__ ew, const float* __restrict__ eb)
{
    int r = blockIdx.x; int b = r >> 7; int n = r & 127;
    int tid = threadIdx.x, w = tid >> 5, lane = tid & 31;
    __shared__ float ts[512];
    __shared__ float accA[16], accT[16], accE[16];
    for (int i=tid;i<512;i+=128) ts[i] = g_T[(size_t)r*512 + i];
    __syncthreads();
    float invt = 1.0f/(22.627416997969522f * fmaxf(temp[0], 0.1f));
    for (int c=w;c<16;c+=4){
        const float* xr = x + ((size_t)b*SEQ + n*CWIN + c)*D;
        float gs=0.f, as=0.f, tws=0.f, es=0.f;
        for (int e=lane;e<512;e+=32){
            float xv = xr[e];
            gs  = fmaf(xv, ts[e], gs);
            as  = fmaf(xv, aw[e], as);
            tws = fmaf(xv, tw[e], tws);
            es  = fmaf(xv, ew[e], es);
        }
        gs = wred(gs); as = wred(as); tws = wred(tws); es = wred(es);
        if (lane==0){
            g_gamma[(size_t)r*CWIN + c] = 1.f/(1.f + expf(-gs*invt));
            accA[c]=as; accT[c]=tws; accE[c]=es;
        }
    }
    __syncthreads();
    if (tid==0){
        float sa=0.f, st=0.f, se=0.f;
        for (int c=0;c<16;c++){ sa+=accA[c]; st+=accT[c]; se+=accE[c]; }
        sa = sa*(1.f/16.f) + ab[0];
        st = st*(1.f/16.f) + tb[0];
        se = se*(1.f/16.f) + eb[0];
        g_alpha[r] = 1.f/(1.f+expf(-sa));
        g_theta[r] = 1.f/(1.f+expf(-st));
        g_eta[r]   = 1.f/(1.f+expf(-se));
    }
}

// ---------------- persistent chunk-recurrence kernel ----------------
// Row-block 0 of M,S (constant poly feature) handled ANALYTICALLY via 5 per-
// column moments (Sm, Ss, Sm2, Ss2, Sms) held by threads tid<16 (one v-pair each).
#define SM_KS   0           // u64[16*512]  splat (k,k)            65536 B
#define SM_QS   65536       // u64[16*512*2] splat q pairs        131072 B (aliased by RED)
#define SM_ERS  196608      // u64[16*16]                           2048 B
#define SM_WRS  198656      // float[16]
#define SM_SBC  198720      // float (pad to 64)
#define SM_PM0  198784      // u64[16]  Σ M0 pre-update
#define SM_YM0  198912      // u64[16]  Σ M0 post-update
#define SM_SQM  199040      // u64[16]  Σ M0² post-update
#define SM_TOT  199168

__global__ void __launch_bounds__(512) chunk_loop_kernel(const float* __restrict__ coeffs)
{
    extern __shared__ char smraw[];
    u64*   KS  = (u64*)(smraw + SM_KS);
    u64*   QS  = (u64*)(smraw + SM_QS);
    u64*   RED = (u64*)(smraw + SM_QS);    // alias [32][16][16]
    u64*   ERS = (u64*)(smraw + SM_ERS);
    float* WRS = (float*)(smraw + SM_WRS);
    float* SBC = (float*)(smraw + SM_SBC);
    u64*   PM0 = (u64*)(smraw + SM_PM0);
    u64*   YM0 = (u64*)(smraw + SM_YM0);
    u64*   SQM = (u64*)(smraw + SM_SQM);

    const int b = blockIdx.y, vt = blockIdx.x;
    const int tid = threadIdx.x;
    const int pi = tid & 15, jg = tid >> 4;
    const int w = tid >> 5, lane = tid & 31;
    const int v0 = vt*32 + 2*pi;
    const int rc = tid >> 4, rpi = tid & 15;   // reduce roles (tid<256)

    const float c0 = coeffs[0], c1 = coeffs[1], c2 = coeffs[2];
    const u64 c0_2 = PK2(c0,c0), c1_2 = PK2(c1,c1), c2_2 = PK2(c2,c2);
    const float f0 = 0.125f*c0, f1 = 0.125f*c1, f2 = 0.125f*c2;

    float* Mb = g_M + (size_t)b*DP*D;
    float* Sb = g_S + (size_t)b*DP*D;

    // ---- initial row-0 moments (threads tid<16; one-time) ----
    u64 Mm1=0ull, Ms1=0ull, Mm2=0ull, Ms2=0ull, Mms=0ull;
    if (tid < 16){
        const float* pm = Mb + vt*32 + 2*tid;
        const float* ps = Sb + vt*32 + 2*tid;
        #pragma unroll 4
        for (int j=0;j<512;j++){
            u64 m = *(const u64*)(pm + (size_t)j*D);
            u64 s = *(const u64*)(ps + (size_t)j*D);
            Mm1 = ADD2(Mm1, m); Ms1 = ADD2(Ms1, s);
            Mm2 = FMA2(m,m,Mm2); Ms2 = FMA2(s,s,Ms2); Mms = FMA2(m,s,Mms);
        }
    }

    u64 yv_pend = 0ull;

    for (int n=0;n<NCH;n++){
        // ---- publish pre-update ΣM0, stage k (splatted) ----
        if (tid < 16) PM0[tid] = Mm1;
        const float* Kc = g_K + ((size_t)b*SEQ + n*CWIN)*D;
        #pragma unroll
        for (int i=0;i<16;i++){
            int idx = tid + i*512;
            float kv = Kc[idx];
            KS[idx] = PK2(kv,kv);
        }
        __syncthreads();

        // ---- phase A: pred partials (rows 1,2 only) ----
        u64 acc[16];
        #pragma unroll
        for (int c=0;c<16;c++) acc[c]=0ull;
        const float* pA = Mb + (size_t)(512+jg)*D + v0;
        u64 m1 = *(const u64*)pA;
        u64 m2 = *(const u64*)(pA + 512*D);
        #pragma unroll 4
        for (int t=0;t<16;t++){
            const float* pN = pA + 32*D;
            u64 nm1=0ull, nm2=0ull;
            if (t<15){ nm1 = *(const u64*)pN; nm2 = *(const u64*)(pN + 512*D); }
            u64 t1 = MUL2(c1_2, m1), t2 = MUL2(c2_2, m2);
            int j = jg + 32*t;
            #pragma unroll
            for (int c=0;c<16;c++){
                u64 kk = KS[c*512 + j];
                acc[c] = FMA2(kk, FMA2(kk, t2, t1), acc[c]);
            }
            m1 = nm1; m2 = nm2; pA = pN;
        }
        #pragma unroll
        for (int c=0;c<16;c++) RED[(jg*16 + c)*16 + pi] = acc[c];
        __syncthreads();

        // ---- pred reduce (tid<256) ----
        u64 p2 = 0ull;
        if (tid < 256){
            u64 ps = 0ull;
            #pragma unroll
            for (int g=0;g<32;g++) ps = ADD2(ps, RED[(g*16 + rc)*16 + rpi]);
            p2 = FMA2(c0_2, PM0[rpi], ps);
        }

        // ---- wait for chunk n-1 norm (overlapped) ----
        if (tid==0 && n>0){
            unsigned target = 16u*(unsigned)n;
            while (atomicAdd(&g_ctr[b], 0u) < target) __nanosleep(32);
            __threadfence();
            float ss = 0.f;
            const float* pp = g_part2 + ((n-1)&1)*BB*16 + b*16;
            #pragma unroll
            for (int i=0;i<16;i++) ss += __ldcg(&pp[i]);
            SBC[0] = fminf(50.0f/(sqrtf(ss)+1e-6f), 1.0f);
        }
        __syncthreads();
        float s_prev = (n>0) ? SBC[0] : 1.0f;

        // ---- write pending y(n-1), compute err(n); all threads stage q ----
        if (tid < 256){
            if (n>0){
                float ya,yb; UNPK(yv_pend, ya, yb);
                *(float2*)&g_Y[((size_t)b*SEQ + (n-1)*CWIN + rc)*D + vt*32 + 2*rpi]
                    = make_float2(s_prev*ya, s_prev*yb);
            }
            float pa,pb; UNPK(p2, pa, pb);
            const float* Vp = g_V + ((size_t)b*SEQ + n*CWIN + rc)*D + vt*32 + 2*rpi;
            float ga = g_gamma[(b*NCH + n)*CWIN + rc];
            float ea = ga*(pa*s_prev - Vp[0]);
            float eb = ga*(pb*s_prev - Vp[1]);
            ERS[rc*16 + rpi] = PK2(ea, eb);
        }
        {
            const float* Qc = g_Q + ((size_t)b*SEQ + n*CWIN)*D;
            #pragma unroll
            for (int i=0;i<16;i++){
                int idx = tid + i*512;
                float qv = Qc[idx];
                float a = c1*qv, bq = c2*qv*qv;
                QS[idx*2+0] = PK2(a,a);
                QS[idx*2+1] = PK2(bq,bq);
            }
        }
        __syncthreads();

        int gi = b*NCH + n;
        float alf = g_alpha[gi]*s_prev, thf = g_theta[gi], etf = g_eta[gi];

        // ---- row-0 moment update (threads tid<16) ----
        if (tid < 16){
            u64 esum = 0ull;
            #pragma unroll
            for (int c=0;c<16;c++) esum = ADD2(esum, ERS[c*16 + tid]);
            float ge = etf*f0;
            u64 g   = MUL2(PK2(ge,ge), esum);
            u64 thv = PK2(thf,thf), alv = PK2(alf,alf);
            u64 s1n = FMA2(thv, Ms1, MUL2(PK2(-512.f,-512.f), g));
            u64 thg = MUL2(thv, g);
            u64 s2n = ADD2( FMA2(MUL2(thv,thv), Ms2, MUL2(PK2(-2.f,-2.f), MUL2(thg, Ms1))),
                            MUL2(PK2(512.f,512.f), MUL2(g,g)) );
            u64 msp = FMA2(thv, Mms, MUL2(MUL2(PK2(-1.f,-1.f), g), Mm1));
            u64 m1n = FMA2(alv, Mm1, s1n);
            u64 m2n = ADD2( FMA2(MUL2(alv,alv), Mm2, MUL2(MUL2(PK2(2.f,2.f), alv), msp)), s2n );
            u64 msn = ADD2(MUL2(alv, msp), s2n);
            Mm1=m1n; Ms1=s1n; Mm2=m2n; Ms2=s2n; Mms=msn;
            YM0[tid] = m1n;
            SQM[tid] = m2n;
        }

        // ---- phase B: grad + update (rows 1,2) + fused y + sumsq ----
        u64 e2[16];
        #pragma unroll
        for (int c=0;c<16;c++) e2[c] = ERS[c*16 + pi];

        u64 al = PK2(alf,alf), th = PK2(thf,thf);
        u64 nf1 = PK2(-etf*f1, -etf*f1);
        u64 nf2 = PK2(-etf*f2, -etf*f2);

        u64 yacc[16];
        #pragma unroll
        for (int c=0;c<16;c++) yacc[c]=0ull;
        u64 sq2 = 0ull;

        float* pM1 = Mb + (size_t)(512+jg)*D + v0;
        float* pS1 = Sb + (size_t)(512+jg)*D + v0;
        u64 mo1 = *(const u64*)pM1, mo2 = *(const u64*)(pM1 + 512*D);
        u64 so1 = *(const u64*)pS1, so2 = *(const u64*)(pS1 + 512*D);
        #pragma unroll 2
        for (int t=0;t<16;t++){
            float* nM1 = pM1 + 32*D; float* nS1 = pS1 + 32*D;
            u64 nmo1=0ull, nmo2=0ull, nso1=0ull, nso2=0ull;
            if (t<15){
                nmo1 = *(const u64*)nM1; nmo2 = *(const u64*)(nM1 + 512*D);
                nso1 = *(const u64*)nS1; nso2 = *(const u64*)(nS1 + 512*D);
            }
            int j = jg + 32*t;
            u64 g1 = 0ull, g2 = 0ull;
            #pragma unroll
            for (int c=0;c<16;c++){
                u64 kk = KS[c*512 + j];
                u64 kk2 = MUL2(kk,kk);
                g1 = FMA2(kk,  e2[c], g1);
                g2 = FMA2(kk2, e2[c], g2);
            }
            u64 sn1 = FMA2(nf1, g1, MUL2(th, so1));
            u64 sn2 = FMA2(nf2, g2, MUL2(th, so2));
            u64 mn1 = FMA2(al, mo1, sn1);
            u64 mn2 = FMA2(al, mo2, sn2);
            *(u64*)(pS1)          = sn1;
            *(u64*)(pS1 + 512*D)  = sn2;
            *(u64*)(pM1)          = mn1;
            *(u64*)(pM1 + 512*D)  = mn2;
            sq2 = FMA2(mn1,mn1,sq2); sq2 = FMA2(mn2,mn2,sq2);
            #pragma unroll
            for (int c=0;c<16;c++){
                ulonglong2 qq = *(const ulonglong2*)&QS[(c*512 + j)*2];
                yacc[c] = FMA2(qq.x, mn1, FMA2(qq.y, mn2, yacc[c]));
            }
            mo1=nmo1; mo2=nmo2; so1=nso1; so2=nso2; pM1=nM1; pS1=nS1;
        }
        float sa,sb; UNPK(sq2, sa, sb);
        float sq = wred(sa + sb);
        if (lane==0) WRS[w] = sq;
        __syncthreads();                       // all t-loops done -> QS dead

        #pragma unroll
        for (int c=0;c<16;c++) RED[(jg*16 + c)*16 + pi] = yacc[c];
        __syncthreads();

        if (tid < 256){
            u64 ys = 0ull;
            #pragma unroll
            for (int g=0;g<32;g++) ys = ADD2(ys, RED[(g*16 + rc)*16 + rpi]);
            yv_pend = FMA2(c0_2, YM0[rpi], ys);
        }
        if (tid==0){
            float tot = 0.f;
            #pragma unroll
            for (int i=0;i<16;i++) tot += WRS[i];
            #pragma unroll
            for (int i=0;i<16;i++){
                float qa,qb; UNPK(SQM[i], qa, qb);
                tot += qa + qb;
            }
            g_part2[(n&1)*BB*16 + b*16 + vt] = tot;
            __threadfence();
            atomicAdd(&g_ctr[b], 1u);
        }
        __syncthreads();
    }

    // ---- tail: y for chunk 127 ----
    if (tid==0){
        unsigned target = 16u*NCH;
        while (atomicAdd(&g_ctr[b], 0u) < target) __nanosleep(32);
        __threadfence();
        float ss = 0.f;
        const float* pp = g_part2 + ((NCH-1)&1)*BB*16 + b*16;
        #pragma unroll
        for (int i=0;i<16;i++) ss += __ldcg(&pp[i]);
        SBC[0] = fminf(50.0f/(sqrtf(ss)+1e-6f), 1.0f);
    }
    __syncthreads();
    if (tid < 256){
        float s = SBC[0];
        float ya,yb; UNPK(yv_pend, ya, yb);
        *(float2*)&g_Y[((size_t)b*SEQ + (NCH-1)*CWIN + rc)*D + vt*32 + 2*rpi]
            = make_float2(s*ya, s*yb);
    }
}

// ---------------- launch ----------------
extern "C" void kernel_launch(void* const* d_in, const int* in_sizes, int n_in,
                              void* d_out, int out_size)
{
    const float* x     = (const float*)d_in[0];
    const float* M0    = (const float*)d_in[1];
    const float* S0    = (const float*)d_in[2];
    const float* Wk    = (const float*)d_in[3];
    const float* Wv    = (const float*)d_in[4];
    const float* Wq    = (const float*)d_in[5];
    const float* Wqk   = (const float*)d_in[6];
    const float* Wout  = (const float*)d_in[7];
    const float* coeffs= (const float*)d_in[8];
    const float* cgWq  = (const float*)d_in[9];
    const float* cgWk  = (const float*)d_in[10];
    const float* temp  = (const float*)d_in[11];
    const float* aw    = (const float*)d_in[12];
    const float* ab    = (const float*)d_in[13];
    const float* tw    = (const float*)d_in[14];
    const float* tb    = (const float*)d_in[15];
    const float* ew    = (const float*)d_in[16];
    const float* eb    = (const float*)d_in[17];
    float* out = (float*)d_out;

    float *pM,*pS,*pK,*pV,*pQ,*pY,*pE,*pXl,*pQG,*pT;
    cudaGetSymbolAddress((void**)&pM,  g_M);
    cudaGetSymbolAddress((void**)&pS,  g_S);
    cudaGetSymbolAddress((void**)&pK,  g_K);
    cudaGetSymbolAddress((void**)&pV,  g_V);
    cudaGetSymbolAddress((void**)&pQ,  g_Q);
    cudaGetSymbolAddress((void**)&pY,  g_Y);
    cudaGetSymbolAddress((void**)&pE,  g_E);
    cudaGetSymbolAddress((void**)&pXl, g_Xlast);
    cudaGetSymbolAddress((void**)&pQG, g_QG);
    cudaGetSymbolAddress((void**)&pT,  g_T);

    cudaFuncSetAttribute(chunk_loop_kernel,
                         cudaFuncAttributeMaxDynamicSharedMemorySize, SM_TOT);

    cudaMemcpyAsync(pM, M0, sizeof(float)*(size_t)BB*DP*D, cudaMemcpyDeviceToDevice);
    cudaMemcpyAsync(pS, S0, sizeof(float)*(size_t)BB*DP*D, cudaMemcpyDeviceToDevice);
    zero_ctrs<<<1,32>>>();

    // fold Wqk@Wq, then the big projections
    gemm_kernel<false><<<dim3(4,4),  256>>>(Wqk, Wq,  pE, 512,   512, 512);
    gemm_kernel<true ><<<dim3(4,128),256>>>(x,   Wk,  pK, BB*SEQ,512, 512);
    gemm_kernel<true ><<<dim3(4,128),256>>>(x,   Wv,  pV, BB*SEQ,512, 512);
    gemm_kernel<true ><<<dim3(4,128),256>>>(x,   pE,  pQ, BB*SEQ,512, 512);

    // gates
    gather_xlast<<<2048,256>>>(x);
    gemm_kernel<true ><<<dim3(4,8),256>>>(pXl, cgWq, pQG, BB*NCH, 512, 512);
    gemm_kernel<false><<<dim3(4,8),256>>>(pQG, cgWk, pT,  BB*NCH, 512, 512);
    gates_kernel<<<BB*NCH,128>>>(x, temp, aw, ab, tw, tb, ew, eb);

    // entire 128-chunk recurrence in ONE persistent kernel
    chunk_loop_kernel<<<dim3(16,8),512,SM_TOT>>>(coeffs);

    // out = Y @ Wout^T
    gemm_kernel<true><<<dim3(4,128),256>>>(pY, Wout, out, BB*SEQ, 512, 512);
}